// round 15
// baseline (speedup 1.0000x reference)
#include <cuda_runtime.h>
#include <cuda_fp16.h>
#include <cstdint>

#define N_NODES 100000
#define E_MAX   1200000
#define HID 64

// ---- static device scratch (allocation-free) ----
__device__ float  g_deg [N_NODES];           // sum of incoming edge weights (no self)
__device__ float  g_hs  [N_NODES * HID];     // raw transformed features (XW), fp32
__device__ __half g_hsh [N_NODES * HID];     // fp16 mirror of g_hs (gather path)
__device__ float  g_act [N_NODES * HID];     // layer-1 activations
__device__ int    g_cnt [N_NODES];           // in-degree count
__device__ int    g_offs[N_NODES];           // CSR exclusive offsets
__device__ int    g_cur [N_NODES];           // binning cursors
__device__ int    g_bsum[512];               // per-block count sums
__device__ int    g_done1;                   // scan phase-1 flag (zeroed in init)
__device__ int    g_done2;                   // scan phase-2 flag (zeroed in init)
__device__ int2   g_csr [E_MAX];             // CSR entry: {src*HID, bits(w*dinv[src])}
__device__ int    g_is32;                    // edge_index dtype flag

// ---- packed f32x2 helpers (Blackwell FFMA2; PTX-only, ptxas won't fuse) ----
__device__ __forceinline__ unsigned long long pack2(float a, float b) {
    unsigned long long r;
    asm("mov.b64 %0, {%1, %2};" : "=l"(r)
        : "r"(__float_as_uint(a)), "r"(__float_as_uint(b)));
    return r;
}
__device__ __forceinline__ float2 unpack2(unsigned long long v) {
    unsigned lo, hi;
    asm("mov.b64 {%0, %1}, %2;" : "=r"(lo), "=r"(hi) : "l"(v));
    return make_float2(__uint_as_float(lo), __uint_as_float(hi));
}
__device__ __forceinline__ void fma2(unsigned long long& d,
                                     unsigned long long a, unsigned long long b) {
    asm("fma.rn.f32x2 %0, %1, %2, %3;" : "=l"(d) : "l"(a), "l"(b), "l"(d));
}

__device__ __forceinline__ void decode_edge(const void* ei, int E, int e,
                                            int& src, int& dst) {
    if (g_is32) {
        const int* p = (const int*)ei;
        src = p[e]; dst = p[E + e];
    } else {
        const long long* p = (const long long*)ei;
        src = (int)p[e]; dst = (int)p[E + e];
    }
}

// ---------------------------------------------------------------------------
// init: zero deg/cnt/flags, detect edge_index dtype.
// ---------------------------------------------------------------------------
__global__ void init_kernel(const void* ei, int n) {
    int i = blockIdx.x * blockDim.x + threadIdx.x;
    if (i < n) { g_deg[i] = 0.0f; g_cnt[i] = 0; }
    if (i == 0) {
        g_done1 = 0;
        g_done2 = 0;
        const long long* p = (const long long*)ei;
        int bad = 0;
        for (int k = 0; k < 64; k++) {
            long long v = p[k];
            if (v < 0 || v >= N_NODES) bad = 1;
        }
        g_is32 = bad;
    }
}

// ---------------------------------------------------------------------------
// Shared GEMM row body with packed FFMA2. Writes the raw row to g_hs (fp32,
// used for the exact self-loop term) AND to g_hsh (fp16 mirror, gather path).
// ---------------------------------------------------------------------------
__device__ __forceinline__ void gemm_row_f32x2(
    const float* __restrict__ in_row, const float* sW, int row)
{
    unsigned long long acc2[HID / 2];
    #pragma unroll
    for (int j = 0; j < HID / 2; j++) acc2[j] = 0ULL;   // bits(+0.0f, +0.0f)

    const float4* xr = (const float4*)in_row;
    #pragma unroll
    for (int k4 = 0; k4 < HID / 4; k4++) {
        float4 xv = __ldg(&xr[k4]);
        float xs[4] = {xv.x, xv.y, xv.z, xv.w};
        #pragma unroll
        for (int s = 0; s < 4; s++) {
            int k = k4 * 4 + s;
            unsigned long long xk2 = pack2(xs[s], xs[s]);
            const ulonglong2* wp = (const ulonglong2*)&sW[k * HID];
            #pragma unroll
            for (int j2 = 0; j2 < HID / 4; j2++) {
                ulonglong2 wv = wp[j2];
                fma2(acc2[2 * j2 + 0], xk2, wv.x);
                fma2(acc2[2 * j2 + 1], xk2, wv.y);
            }
        }
    }

    float4* ph = (float4*)&g_hs[(size_t)row * HID];
    uint2*  mh = (uint2*)&g_hsh[(size_t)row * HID];
    #pragma unroll
    for (int j4 = 0; j4 < HID / 4; j4++) {
        float2 p0 = unpack2(acc2[2 * j4 + 0]);
        float2 p1 = unpack2(acc2[2 * j4 + 1]);
        ph[j4] = make_float4(p0.x, p0.y, p1.x, p1.y);
        __half2 q0 = __floats2half2_rn(p0.x, p0.y);
        __half2 q1 = __floats2half2_rn(p1.x, p1.y);
        mh[j4] = make_uint2(*(unsigned*)&q0, *(unsigned*)&q1);
    }
}

// ---------------------------------------------------------------------------
// Fused: blocks [0, gE) run the edge histogram (cnt++/deg+=w atomics);
// blocks [gE, gE+gN) run the layer-1 GEMM rows (hs = x @ W1, unscaled).
// ---------------------------------------------------------------------------
__global__ __launch_bounds__(256) void hist_gemm1_kernel(
    const void* ei, const float* __restrict__ w,
    const float* __restrict__ x, const float* __restrict__ W,
    int n, int E, int gE)
{
    if ((int)blockIdx.x < gE) {
        int e = blockIdx.x * blockDim.x + threadIdx.x;
        if (e >= E) return;
        int src, dst;
        decode_edge(ei, E, e, src, dst);
        atomicAdd(&g_cnt[dst], 1);
        atomicAdd(&g_deg[dst], w[e]);
        return;
    }

    __shared__ __align__(16) float sW[HID * HID];
    for (int i = threadIdx.x; i < HID * HID; i += blockDim.x) sW[i] = W[i];
    __syncthreads();

    int row = (blockIdx.x - gE) * blockDim.x + threadIdx.x;
    if (row >= n) return;
    gemm_row_f32x2(x + (size_t)row * HID, sW, row);
}

// ---------------------------------------------------------------------------
// Fused scan + bin, one kernel (grid = gE blocks). Deadlock-free: the
// nsb=391 scan blocks all fit in wave 1.
// ---------------------------------------------------------------------------
__global__ __launch_bounds__(256) void scanbin_kernel(
    const void* ei, const float* __restrict__ w, int n, int E, int nsb)
{
    __shared__ int s[256];
    int t = threadIdx.x;
    int bid = blockIdx.x;

    if (bid < nsb) {
        int i = bid * 256 + t;
        int v = (i < n) ? g_cnt[i] : 0;
        s[t] = v; __syncthreads();
        #pragma unroll
        for (int d = 1; d < 256; d <<= 1) {
            int x = (t >= d) ? s[t - d] : 0;
            __syncthreads();
            s[t] += x; __syncthreads();
        }
        int excl = s[t] - v;                    // exclusive within block

        if (t == 255) {
            g_bsum[bid] = s[255];
            __threadfence();
            atomicAdd(&g_done1, 1);
        }
        if (t == 0) {
            while (atomicAdd(&g_done1, 0) < nsb) __nanosleep(64);
        }
        __syncthreads();

        int p = 0;
        for (int b = t; b < bid; b += 256) p += g_bsum[b];
        s[t] = p; __syncthreads();
        #pragma unroll
        for (int d = 128; d > 0; d >>= 1) {
            if (t < d) s[t] += s[t + d];
            __syncthreads();
        }
        int prefix = s[0];
        if (i < n) {
            int o = excl + prefix;
            g_offs[i] = o;
            g_cur[i]  = o;
        }
        __syncthreads();
        if (t == 0) {
            __threadfence();
            atomicAdd(&g_done2, 1);
        }
    }

    // ---- phase B: everyone waits for all cursors, then bins ----
    if (t == 0) {
        while (atomicAdd(&g_done2, 0) < nsb) __nanosleep(64);
    }
    __syncthreads();

    int e = bid * 256 + t;
    if (e >= E) return;
    int src, dst;
    decode_edge(ei, E, e, src, dst);
    float wn = w[e] * rsqrtf(1.0f + g_deg[src]);
    int pos = atomicAdd(&g_cur[dst], 1);
    g_csr[pos] = make_int2(src * HID, __float_as_int(wn));  // pre-multiplied idx
}

// ---------------------------------------------------------------------------
// Layer-2 GEMM: hs = g_act @ W2 (raw). g_act referenced inside device code.
// ---------------------------------------------------------------------------
__global__ __launch_bounds__(256) void gemm2_kernel(
    const float* __restrict__ W, int n)
{
    __shared__ __align__(16) float sW[HID * HID];
    for (int i = threadIdx.x; i < HID * HID; i += blockDim.x) sW[i] = W[i];
    __syncthreads();

    int row = blockIdx.x * blockDim.x + threadIdx.x;
    if (row >= n) return;
    gemm_row_f32x2((const float*)g_act + (size_t)row * HID, sW, row);
}

// ---------------------------------------------------------------------------
// Aggregation: one warp per dst (R11 structure: regs ~32, high occ). Lane l
// owns features [2l, 2l+1]. Neighbor messages gathered from the fp16 mirror:
// a warp row-read = 128B = ONE L1 wavefront (vs 2 for fp32) -> halves the
// L2-data traffic that bounds this kernel. Self-loop term stays exact fp32.
// 4 independent accumulator chains.
//   MODE 0: g_act = relu(dinv*acc + bias);  MODE 1: outp = dinv*acc + bias
// ---------------------------------------------------------------------------
template <int MODE>
__global__ __launch_bounds__(256) void agg_kernel(
    const float* __restrict__ bias, float* __restrict__ outp, int n)
{
    int gtid = blockIdx.x * blockDim.x + threadIdx.x;
    int dst  = gtid >> 5;
    if (dst >= n) return;
    int lane = threadIdx.x & 31;

    int beg = g_offs[dst];
    int cnt = g_cnt[dst];
    float di = rsqrtf(1.0f + g_deg[dst]);

    const __half* hshl = (const __half*)g_hsh + lane * 2;  // fp16 gather base

    float2 hself = *(const float2*)(g_hs + (size_t)dst * HID + lane * 2);
    float ax0 = di * hself.x, ay0 = di * hself.y;          // exact self-loop
    float ax1 = 0.f, ay1 = 0.f, ax2 = 0.f, ay2 = 0.f, ax3 = 0.f, ay3 = 0.f;

    int t = 0;
    for (; t + 4 <= cnt; t += 4) {
        int2 e0 = __ldg(&g_csr[beg + t + 0]);
        int2 e1 = __ldg(&g_csr[beg + t + 1]);
        int2 e2 = __ldg(&g_csr[beg + t + 2]);
        int2 e3 = __ldg(&g_csr[beg + t + 3]);
        unsigned u0 = __ldg((const unsigned*)(hshl + e0.x));
        unsigned u1 = __ldg((const unsigned*)(hshl + e1.x));
        unsigned u2 = __ldg((const unsigned*)(hshl + e2.x));
        unsigned u3 = __ldg((const unsigned*)(hshl + e3.x));
        float w0 = __int_as_float(e0.y), w1 = __int_as_float(e1.y);
        float w2 = __int_as_float(e2.y), w3 = __int_as_float(e3.y);
        float2 f0 = __half22float2(*(__half2*)&u0);
        float2 f1 = __half22float2(*(__half2*)&u1);
        float2 f2 = __half22float2(*(__half2*)&u2);
        float2 f3 = __half22float2(*(__half2*)&u3);
        ax0 += w0 * f0.x; ay0 += w0 * f0.y;
        ax1 += w1 * f1.x; ay1 += w1 * f1.y;
        ax2 += w2 * f2.x; ay2 += w2 * f2.y;
        ax3 += w3 * f3.x; ay3 += w3 * f3.y;
    }
    for (; t < cnt; t++) {
        int2 e0 = __ldg(&g_csr[beg + t]);
        unsigned u0 = __ldg((const unsigned*)(hshl + e0.x));
        float w0 = __int_as_float(e0.y);
        float2 f0 = __half22float2(*(__half2*)&u0);
        ax0 += w0 * f0.x; ay0 += w0 * f0.y;
    }

    float ax = (ax0 + ax1) + (ax2 + ax3);
    float ay = (ay0 + ay1) + (ay2 + ay3);
    float bx = bias[lane * 2], by = bias[lane * 2 + 1];
    float ox = di * ax + bx;
    float oy = di * ay + by;
    if (MODE == 0) {
        ox = fmaxf(ox, 0.0f);
        oy = fmaxf(oy, 0.0f);
        *(float2*)&g_act[(size_t)dst * HID + lane * 2] = make_float2(ox, oy);
    } else {
        *(float2*)&outp[(size_t)dst * HID + lane * 2] = make_float2(ox, oy);
    }
}

extern "C" void kernel_launch(void* const* d_in, const int* in_sizes, int n_in,
                              void* d_out, int out_size)
{
    const float* x  = (const float*)d_in[0];
    const void*  ei = d_in[1];               // int32 or int64, device-detected
    const float* ew = (const float*)d_in[2];
    const float* W1 = (const float*)d_in[3];
    const float* b1 = (const float*)d_in[4];
    const float* W2 = (const float*)d_in[5];
    const float* b2 = (const float*)d_in[6];
    float* out = (float*)d_out;

    int n = in_sizes[0] / HID;
    int E = in_sizes[2];

    const int T = 256;
    int gN   = (n + T - 1) / T;              // 391
    int gE   = (E + T - 1) / T;              // 4688
    int gN32 = (n * 32 + T - 1) / T;         // warp-per-node

    init_kernel      <<<gN, T>>>(ei, n);                         // 0
    hist_gemm1_kernel<<<gE + gN, T>>>(ei, ew, x, W1, n, E, gE);  // 1
    scanbin_kernel   <<<gE, T>>>(ei, ew, n, E, gN);              // 2

    agg_kernel<0><<<gN32, T>>>(b1, nullptr, n);                  // 3 (profiled)
    gemm2_kernel <<<gN, T>>>(W2, n);                             // 4
    agg_kernel<1><<<gN32, T>>>(b2, out, n);                      // 5
}

// round 16
// speedup vs baseline: 1.1011x; 1.1011x over previous
#include <cuda_runtime.h>
#include <cstdint>

#define N_NODES 100000
#define E_MAX   1200000
#define HID 64

// ---- static device scratch (allocation-free) ----
__device__ float g_deg [N_NODES];            // sum of incoming edge weights (no self)
__device__ float g_hs  [N_NODES * HID];      // raw transformed features (XW)
__device__ float g_act [N_NODES * HID];      // layer-1 activations
__device__ int   g_cnt [N_NODES];            // in-degree count
__device__ int   g_offs[N_NODES];            // CSR exclusive offsets
__device__ int   g_epos[E_MAX];              // per-edge rank within its dst (from hist)
__device__ int   g_bsum[512];                // per-block count sums
__device__ int   g_done1;                    // scan phase-1 flag (zeroed in init)
__device__ int   g_done2;                    // scan phase-2 flag (zeroed in init)
__device__ int2  g_csr [E_MAX];              // CSR entry: {src*HID, bits(w*dinv[src])}
__device__ int   g_is32;                     // edge_index dtype flag

// ---- packed f32x2 helpers (Blackwell FFMA2; PTX-only, ptxas won't fuse) ----
__device__ __forceinline__ unsigned long long pack2(float a, float b) {
    unsigned long long r;
    asm("mov.b64 %0, {%1, %2};" : "=l"(r)
        : "r"(__float_as_uint(a)), "r"(__float_as_uint(b)));
    return r;
}
__device__ __forceinline__ float2 unpack2(unsigned long long v) {
    unsigned lo, hi;
    asm("mov.b64 {%0, %1}, %2;" : "=r"(lo), "=r"(hi) : "l"(v));
    return make_float2(__uint_as_float(lo), __uint_as_float(hi));
}
__device__ __forceinline__ void fma2(unsigned long long& d,
                                     unsigned long long a, unsigned long long b) {
    asm("fma.rn.f32x2 %0, %1, %2, %3;" : "=l"(d) : "l"(a), "l"(b), "l"(d));
}

__device__ __forceinline__ void decode_edge(const void* ei, int E, int e,
                                            int& src, int& dst) {
    if (g_is32) {
        const int* p = (const int*)ei;
        src = p[e]; dst = p[E + e];
    } else {
        const long long* p = (const long long*)ei;
        src = (int)p[e]; dst = (int)p[E + e];
    }
}

// ---------------------------------------------------------------------------
// init: zero deg/cnt/flags, detect edge_index dtype.
// ---------------------------------------------------------------------------
__global__ void init_kernel(const void* ei, int n) {
    int i = blockIdx.x * blockDim.x + threadIdx.x;
    if (i < n) { g_deg[i] = 0.0f; g_cnt[i] = 0; }
    if (i == 0) {
        g_done1 = 0;
        g_done2 = 0;
        const long long* p = (const long long*)ei;
        int bad = 0;
        for (int k = 0; k < 64; k++) {
            long long v = p[k];
            if (v < 0 || v >= N_NODES) bad = 1;
        }
        g_is32 = bad;
    }
}

// ---------------------------------------------------------------------------
// Shared GEMM row body with packed FFMA2. Writes raw (unscaled) row to g_hs.
// ---------------------------------------------------------------------------
__device__ __forceinline__ void gemm_row_f32x2(
    const float* __restrict__ in_row, const float* sW, int row)
{
    unsigned long long acc2[HID / 2];
    #pragma unroll
    for (int j = 0; j < HID / 2; j++) acc2[j] = 0ULL;   // bits(+0.0f, +0.0f)

    const float4* xr = (const float4*)in_row;
    #pragma unroll
    for (int k4 = 0; k4 < HID / 4; k4++) {
        float4 xv = __ldg(&xr[k4]);
        float xs[4] = {xv.x, xv.y, xv.z, xv.w};
        #pragma unroll
        for (int s = 0; s < 4; s++) {
            int k = k4 * 4 + s;
            unsigned long long xk2 = pack2(xs[s], xs[s]);
            const ulonglong2* wp = (const ulonglong2*)&sW[k * HID];
            #pragma unroll
            for (int j2 = 0; j2 < HID / 4; j2++) {
                ulonglong2 wv = wp[j2];
                fma2(acc2[2 * j2 + 0], xk2, wv.x);
                fma2(acc2[2 * j2 + 1], xk2, wv.y);
            }
        }
    }

    float4* ph = (float4*)&g_hs[(size_t)row * HID];
    #pragma unroll
    for (int j4 = 0; j4 < HID / 4; j4++) {
        float2 p0 = unpack2(acc2[2 * j4 + 0]);
        float2 p1 = unpack2(acc2[2 * j4 + 1]);
        ph[j4] = make_float4(p0.x, p0.y, p1.x, p1.y);
    }
}

// ---------------------------------------------------------------------------
// Fused: blocks [0, gE) run the edge histogram; the atomicAdd return value
// is each edge's rank within its dst segment -> stored to g_epos (coalesced)
// so the bin phase needs NO cursor atomics. Blocks [gE, gE+gN) run the
// layer-1 GEMM rows (hs = x @ W1, unscaled).
// ---------------------------------------------------------------------------
__global__ __launch_bounds__(256) void hist_gemm1_kernel(
    const void* ei, const float* __restrict__ w,
    const float* __restrict__ x, const float* __restrict__ W,
    int n, int E, int gE)
{
    if ((int)blockIdx.x < gE) {
        int e = blockIdx.x * blockDim.x + threadIdx.x;
        if (e >= E) return;
        int src, dst;
        decode_edge(ei, E, e, src, dst);
        int pos = atomicAdd(&g_cnt[dst], 1);
        g_epos[e] = pos;
        atomicAdd(&g_deg[dst], w[e]);
        return;
    }

    __shared__ __align__(16) float sW[HID * HID];
    for (int i = threadIdx.x; i < HID * HID; i += blockDim.x) sW[i] = W[i];
    __syncthreads();

    int row = (blockIdx.x - gE) * blockDim.x + threadIdx.x;
    if (row >= n) return;
    gemm_row_f32x2(x + (size_t)row * HID, sW, row);
}

// ---------------------------------------------------------------------------
// Fused scan + bin, one kernel (grid = gE blocks). Phase A: scan g_cnt into
// g_offs (nsb=391 blocks, all wave-1 resident -> deadlock-free). Phase B:
// every block bins its edge slice atomic-free via offs[dst] + epos[e].
// ---------------------------------------------------------------------------
__global__ __launch_bounds__(256) void scanbin_kernel(
    const void* ei, const float* __restrict__ w, int n, int E, int nsb)
{
    __shared__ int s[256];
    int t = threadIdx.x;
    int bid = blockIdx.x;

    if (bid < nsb) {
        int i = bid * 256 + t;
        int v = (i < n) ? g_cnt[i] : 0;
        s[t] = v; __syncthreads();
        #pragma unroll
        for (int d = 1; d < 256; d <<= 1) {
            int x = (t >= d) ? s[t - d] : 0;
            __syncthreads();
            s[t] += x; __syncthreads();
        }
        int excl = s[t] - v;                    // exclusive within block

        if (t == 255) {
            g_bsum[bid] = s[255];
            __threadfence();
            atomicAdd(&g_done1, 1);
        }
        if (t == 0) {
            while (atomicAdd(&g_done1, 0) < nsb) __nanosleep(64);
        }
        __syncthreads();

        int p = 0;
        for (int b = t; b < bid; b += 256) p += g_bsum[b];
        s[t] = p; __syncthreads();
        #pragma unroll
        for (int d = 128; d > 0; d >>= 1) {
            if (t < d) s[t] += s[t + d];
            __syncthreads();
        }
        int prefix = s[0];
        if (i < n) g_offs[i] = excl + prefix;
        __syncthreads();
        if (t == 0) {
            __threadfence();
            atomicAdd(&g_done2, 1);
        }
    }

    // ---- phase B: wait for all offsets, then bin (atomic-free) ----
    if (t == 0) {
        while (atomicAdd(&g_done2, 0) < nsb) __nanosleep(64);
    }
    __syncthreads();

    int e = bid * 256 + t;
    if (e >= E) return;
    int src, dst;
    decode_edge(ei, E, e, src, dst);
    float wn = w[e] * rsqrtf(1.0f + g_deg[src]);
    int pos = g_offs[dst] + g_epos[e];
    g_csr[pos] = make_int2(src * HID, __float_as_int(wn));  // pre-multiplied idx
}

// ---------------------------------------------------------------------------
// Layer-2 GEMM: hs = g_act @ W2 (raw). g_act referenced inside device code.
// ---------------------------------------------------------------------------
__global__ __launch_bounds__(256) void gemm2_kernel(
    const float* __restrict__ W, int n)
{
    __shared__ __align__(16) float sW[HID * HID];
    for (int i = threadIdx.x; i < HID * HID; i += blockDim.x) sW[i] = W[i];
    __syncthreads();

    int row = blockIdx.x * blockDim.x + threadIdx.x;
    if (row >= n) return;
    gemm_row_f32x2((const float*)g_act + (size_t)row * HID, sW, row);
}

// ---------------------------------------------------------------------------
// Aggregation (R11 champion structure: 32 regs, max occupancy). One warp per
// dst; lane l owns features [2l, 2l+1] packed. Warp-uniform sequential CSR
// loads; 4 independent accumulator chains.
//   MODE 0: g_act = relu(dinv*acc + bias);  MODE 1: outp = dinv*acc + bias
// ---------------------------------------------------------------------------
template <int MODE>
__global__ __launch_bounds__(256) void agg_kernel(
    const float* __restrict__ bias, float* __restrict__ outp, int n)
{
    int gtid = blockIdx.x * blockDim.x + threadIdx.x;
    int dst  = gtid >> 5;
    if (dst >= n) return;
    int lane = threadIdx.x & 31;

    int beg = g_offs[dst];
    int cnt = g_cnt[dst];
    float di = rsqrtf(1.0f + g_deg[dst]);

    const float* hsl = g_hs + lane * 2;        // lane-offset base

    float2 hself = *(const float2*)(hsl + (size_t)dst * HID);
    unsigned long long accA = pack2(di * hself.x, di * hself.y);  // self-loop
    unsigned long long accB = 0ULL, accC = 0ULL, accD = 0ULL;

    int t = 0;
    for (; t + 4 <= cnt; t += 4) {
        int2 e0 = __ldg(&g_csr[beg + t + 0]);
        int2 e1 = __ldg(&g_csr[beg + t + 1]);
        int2 e2 = __ldg(&g_csr[beg + t + 2]);
        int2 e3 = __ldg(&g_csr[beg + t + 3]);
        unsigned long long h0 = __ldg((const unsigned long long*)(hsl + e0.x));
        unsigned long long h1 = __ldg((const unsigned long long*)(hsl + e1.x));
        unsigned long long h2 = __ldg((const unsigned long long*)(hsl + e2.x));
        unsigned long long h3 = __ldg((const unsigned long long*)(hsl + e3.x));
        float w0 = __int_as_float(e0.y), w1 = __int_as_float(e1.y);
        float w2 = __int_as_float(e2.y), w3 = __int_as_float(e3.y);
        fma2(accA, pack2(w0, w0), h0);
        fma2(accB, pack2(w1, w1), h1);
        fma2(accC, pack2(w2, w2), h2);
        fma2(accD, pack2(w3, w3), h3);
    }
    for (; t < cnt; t++) {
        int2 e0 = __ldg(&g_csr[beg + t]);
        unsigned long long h0 = __ldg((const unsigned long long*)(hsl + e0.x));
        float w0 = __int_as_float(e0.y);
        fma2(accA, pack2(w0, w0), h0);
    }

    float2 a = unpack2(accA);
    float2 b = unpack2(accB);
    float2 c = unpack2(accC);
    float2 d = unpack2(accD);
    float ax = (a.x + b.x) + (c.x + d.x);
    float ay = (a.y + b.y) + (c.y + d.y);
    float bx = bias[lane * 2], by = bias[lane * 2 + 1];
    float ox = di * ax + bx;
    float oy = di * ay + by;
    if (MODE == 0) {
        ox = fmaxf(ox, 0.0f);
        oy = fmaxf(oy, 0.0f);
        *(float2*)&g_act[(size_t)dst * HID + lane * 2] = make_float2(ox, oy);
    } else {
        *(float2*)&outp[(size_t)dst * HID + lane * 2] = make_float2(ox, oy);
    }
}

extern "C" void kernel_launch(void* const* d_in, const int* in_sizes, int n_in,
                              void* d_out, int out_size)
{
    const float* x  = (const float*)d_in[0];
    const void*  ei = d_in[1];               // int32 or int64, device-detected
    const float* ew = (const float*)d_in[2];
    const float* W1 = (const float*)d_in[3];
    const float* b1 = (const float*)d_in[4];
    const float* W2 = (const float*)d_in[5];
    const float* b2 = (const float*)d_in[6];
    float* out = (float*)d_out;

    int n = in_sizes[0] / HID;
    int E = in_sizes[2];

    const int T = 256;
    int gN   = (n + T - 1) / T;              // 391
    int gE   = (E + T - 1) / T;              // 4688
    int gN32 = (n * 32 + T - 1) / T;         // warp-per-node

    init_kernel      <<<gN, T>>>(ei, n);                         // 0
    hist_gemm1_kernel<<<gE + gN, T>>>(ei, ew, x, W1, n, E, gE);  // 1
    scanbin_kernel   <<<gE, T>>>(ei, ew, n, E, gN);              // 2

    agg_kernel<0><<<gN32, T>>>(b1, nullptr, n);                  // 3 (profiled)
    gemm2_kernel <<<gN, T>>>(W2, n);                             // 4
    agg_kernel<1><<<gN32, T>>>(b2, out, n);                      // 5
}

// round 17
// speedup vs baseline: 1.1620x; 1.0553x over previous
#include <cuda_runtime.h>
#include <cstdint>

#define N_NODES 100000
#define E_MAX   1200000
#define HID 64

// ---- static device scratch (allocation-free) ----
__device__ float g_deg [N_NODES];            // sum of incoming edge weights (no self)
__device__ float g_hs  [N_NODES * HID];      // raw transformed features (XW)
__device__ float g_act [N_NODES * HID];      // layer-1 activations
__device__ int   g_cnt [N_NODES];            // in-degree count
__device__ int   g_offs[N_NODES];            // CSR exclusive offsets
__device__ int   g_epos[E_MAX];              // per-edge rank within its dst (from hist)
__device__ int   g_bsum[512];                // per-block count sums
__device__ int   g_done1;                    // scan phase-1 flag (zeroed in init)
__device__ int   g_done2;                    // scan phase-2 flag (zeroed in init)
__device__ int2  g_csr [E_MAX];              // CSR entry: {src*HID, bits(w*dinv[src])}
__device__ int   g_is32;                     // edge_index dtype flag

// ---- packed f32x2 helpers (Blackwell FFMA2; PTX-only, ptxas won't fuse) ----
__device__ __forceinline__ unsigned long long pack2(float a, float b) {
    unsigned long long r;
    asm("mov.b64 %0, {%1, %2};" : "=l"(r)
        : "r"(__float_as_uint(a)), "r"(__float_as_uint(b)));
    return r;
}
__device__ __forceinline__ float2 unpack2(unsigned long long v) {
    unsigned lo, hi;
    asm("mov.b64 {%0, %1}, %2;" : "=r"(lo), "=r"(hi) : "l"(v));
    return make_float2(__uint_as_float(lo), __uint_as_float(hi));
}
__device__ __forceinline__ void fma2(unsigned long long& d,
                                     unsigned long long a, unsigned long long b) {
    asm("fma.rn.f32x2 %0, %1, %2, %3;" : "=l"(d) : "l"(a), "l"(b), "l"(d));
}

__device__ __forceinline__ void decode_edge(const void* ei, int E, int e,
                                            int& src, int& dst) {
    if (g_is32) {
        const int* p = (const int*)ei;
        src = p[e]; dst = p[E + e];
    } else {
        const long long* p = (const long long*)ei;
        src = (int)p[e]; dst = (int)p[E + e];
    }
}

// ---------------------------------------------------------------------------
// init: zero deg/cnt/flags, detect edge_index dtype.
// ---------------------------------------------------------------------------
__global__ void init_kernel(const void* ei, int n) {
    int i = blockIdx.x * blockDim.x + threadIdx.x;
    if (i < n) { g_deg[i] = 0.0f; g_cnt[i] = 0; }
    if (i == 0) {
        g_done1 = 0;
        g_done2 = 0;
        const long long* p = (const long long*)ei;
        int bad = 0;
        for (int k = 0; k < 64; k++) {
            long long v = p[k];
            if (v < 0 || v >= N_NODES) bad = 1;
        }
        g_is32 = bad;
    }
}

// ---------------------------------------------------------------------------
// Shared GEMM row body with packed FFMA2. Writes raw (unscaled) row to g_hs.
// ---------------------------------------------------------------------------
__device__ __forceinline__ void gemm_row_f32x2(
    const float* __restrict__ in_row, const float* sW, int row)
{
    unsigned long long acc2[HID / 2];
    #pragma unroll
    for (int j = 0; j < HID / 2; j++) acc2[j] = 0ULL;   // bits(+0.0f, +0.0f)

    const float4* xr = (const float4*)in_row;
    #pragma unroll
    for (int k4 = 0; k4 < HID / 4; k4++) {
        float4 xv = __ldg(&xr[k4]);
        float xs[4] = {xv.x, xv.y, xv.z, xv.w};
        #pragma unroll
        for (int s = 0; s < 4; s++) {
            int k = k4 * 4 + s;
            unsigned long long xk2 = pack2(xs[s], xs[s]);
            const ulonglong2* wp = (const ulonglong2*)&sW[k * HID];
            #pragma unroll
            for (int j2 = 0; j2 < HID / 4; j2++) {
                ulonglong2 wv = wp[j2];
                fma2(acc2[2 * j2 + 0], xk2, wv.x);
                fma2(acc2[2 * j2 + 1], xk2, wv.y);
            }
        }
    }

    float4* ph = (float4*)&g_hs[(size_t)row * HID];
    #pragma unroll
    for (int j4 = 0; j4 < HID / 4; j4++) {
        float2 p0 = unpack2(acc2[2 * j4 + 0]);
        float2 p1 = unpack2(acc2[2 * j4 + 1]);
        ph[j4] = make_float4(p0.x, p0.y, p1.x, p1.y);
    }
}

// ---------------------------------------------------------------------------
// Fused: blocks [0, gE) run the edge histogram; the atomicAdd return value
// is each edge's rank within its dst segment -> stored to g_epos (coalesced)
// so the bin phase needs NO cursor atomics. Blocks [gE, gE+gN) run the
// layer-1 GEMM rows (hs = x @ W1, unscaled).
// ---------------------------------------------------------------------------
__global__ __launch_bounds__(256) void hist_gemm1_kernel(
    const void* ei, const float* __restrict__ w,
    const float* __restrict__ x, const float* __restrict__ W,
    int n, int E, int gE)
{
    if ((int)blockIdx.x < gE) {
        int e = blockIdx.x * blockDim.x + threadIdx.x;
        if (e >= E) return;
        int src, dst;
        decode_edge(ei, E, e, src, dst);
        int pos = atomicAdd(&g_cnt[dst], 1);
        g_epos[e] = pos;
        atomicAdd(&g_deg[dst], w[e]);
        return;
    }

    __shared__ __align__(16) float sW[HID * HID];
    for (int i = threadIdx.x; i < HID * HID; i += blockDim.x) sW[i] = W[i];
    __syncthreads();

    int row = (blockIdx.x - gE) * blockDim.x + threadIdx.x;
    if (row >= n) return;
    gemm_row_f32x2(x + (size_t)row * HID, sW, row);
}

// ---------------------------------------------------------------------------
// Fused scan + bin, one kernel (grid = gE blocks). Phase A: scan g_cnt into
// g_offs (nsb=391 blocks, all wave-1 resident -> deadlock-free). Phase B:
// every block bins its edge slice atomic-free via offs[dst] + epos[e].
// ---------------------------------------------------------------------------
__global__ __launch_bounds__(256) void scanbin_kernel(
    const void* ei, const float* __restrict__ w, int n, int E, int nsb)
{
    __shared__ int s[256];
    int t = threadIdx.x;
    int bid = blockIdx.x;

    if (bid < nsb) {
        int i = bid * 256 + t;
        int v = (i < n) ? g_cnt[i] : 0;
        s[t] = v; __syncthreads();
        #pragma unroll
        for (int d = 1; d < 256; d <<= 1) {
            int x = (t >= d) ? s[t - d] : 0;
            __syncthreads();
            s[t] += x; __syncthreads();
        }
        int excl = s[t] - v;                    // exclusive within block

        if (t == 255) {
            g_bsum[bid] = s[255];
            __threadfence();
            atomicAdd(&g_done1, 1);
        }
        if (t == 0) {
            while (atomicAdd(&g_done1, 0) < nsb) __nanosleep(64);
        }
        __syncthreads();

        int p = 0;
        for (int b = t; b < bid; b += 256) p += g_bsum[b];
        s[t] = p; __syncthreads();
        #pragma unroll
        for (int d = 128; d > 0; d >>= 1) {
            if (t < d) s[t] += s[t + d];
            __syncthreads();
        }
        int prefix = s[0];
        if (i < n) g_offs[i] = excl + prefix;
        __syncthreads();
        if (t == 0) {
            __threadfence();
            atomicAdd(&g_done2, 1);
        }
    }

    // ---- phase B: wait for all offsets, then bin (atomic-free) ----
    if (t == 0) {
        while (atomicAdd(&g_done2, 0) < nsb) __nanosleep(64);
    }
    __syncthreads();

    int e = bid * 256 + t;
    if (e >= E) return;
    int src, dst;
    decode_edge(ei, E, e, src, dst);
    float wn = w[e] * rsqrtf(1.0f + g_deg[src]);
    int pos = g_offs[dst] + g_epos[e];
    g_csr[pos] = make_int2(src * HID, __float_as_int(wn));  // pre-multiplied idx
}

// ---------------------------------------------------------------------------
// Layer-2 GEMM: hs = g_act @ W2 (raw). g_act referenced inside device code.
// ---------------------------------------------------------------------------
__global__ __launch_bounds__(256) void gemm2_kernel(
    const float* __restrict__ W, int n)
{
    __shared__ __align__(16) float sW[HID * HID];
    for (int i = threadIdx.x; i < HID * HID; i += blockDim.x) sW[i] = W[i];
    __syncthreads();

    int row = blockIdx.x * blockDim.x + threadIdx.x;
    if (row >= n) return;
    gemm_row_f32x2((const float*)g_act + (size_t)row * HID, sW, row);
}

// ---------------------------------------------------------------------------
// Aggregation: GRID-STRIDE quasi-persistent variant of the R11 champion.
// Exactly 1184 blocks (148 SM x 8 resident, one wave): each warp loops over
// dsts with stride = total warps, amortizing block prologue/epilogue and
// eliminating CTA churn (the measured 80% -> ~100% achieved-occupancy gap).
// Inner body identical: warp-uniform CSR loads, 4 accumulator chains,
// __launch_bounds__(256, 8) pins regs <= 32 so 8 blocks/SM holds.
//   MODE 0: g_act = relu(dinv*acc + bias);  MODE 1: outp = dinv*acc + bias
// ---------------------------------------------------------------------------
template <int MODE>
__global__ __launch_bounds__(256, 8) void agg_kernel(
    const float* __restrict__ bias, float* __restrict__ outp,
    int n, int nwarps)
{
    int warp_gid = (blockIdx.x * blockDim.x + threadIdx.x) >> 5;
    int lane = threadIdx.x & 31;
    const float* hsl = g_hs + lane * 2;        // lane-offset base
    float bx = bias[lane * 2], by = bias[lane * 2 + 1];

    for (int dst = warp_gid; dst < n; dst += nwarps) {
        int beg = g_offs[dst];
        int cnt = g_cnt[dst];
        float di = rsqrtf(1.0f + g_deg[dst]);

        float2 hself = *(const float2*)(hsl + (size_t)dst * HID);
        unsigned long long accA = pack2(di * hself.x, di * hself.y);  // self
        unsigned long long accB = 0ULL, accC = 0ULL, accD = 0ULL;

        int t = 0;
        for (; t + 4 <= cnt; t += 4) {
            int2 e0 = __ldg(&g_csr[beg + t + 0]);
            int2 e1 = __ldg(&g_csr[beg + t + 1]);
            int2 e2 = __ldg(&g_csr[beg + t + 2]);
            int2 e3 = __ldg(&g_csr[beg + t + 3]);
            unsigned long long h0 = __ldg((const unsigned long long*)(hsl + e0.x));
            unsigned long long h1 = __ldg((const unsigned long long*)(hsl + e1.x));
            unsigned long long h2 = __ldg((const unsigned long long*)(hsl + e2.x));
            unsigned long long h3 = __ldg((const unsigned long long*)(hsl + e3.x));
            float w0 = __int_as_float(e0.y), w1 = __int_as_float(e1.y);
            float w2 = __int_as_float(e2.y), w3 = __int_as_float(e3.y);
            fma2(accA, pack2(w0, w0), h0);
            fma2(accB, pack2(w1, w1), h1);
            fma2(accC, pack2(w2, w2), h2);
            fma2(accD, pack2(w3, w3), h3);
        }
        for (; t < cnt; t++) {
            int2 e0 = __ldg(&g_csr[beg + t]);
            unsigned long long h0 = __ldg((const unsigned long long*)(hsl + e0.x));
            float w0 = __int_as_float(e0.y);
            fma2(accA, pack2(w0, w0), h0);
        }

        float2 a = unpack2(accA);
        float2 b = unpack2(accB);
        float2 c = unpack2(accC);
        float2 d = unpack2(accD);
        float ax = (a.x + b.x) + (c.x + d.x);
        float ay = (a.y + b.y) + (c.y + d.y);
        float ox = di * ax + bx;
        float oy = di * ay + by;
        if (MODE == 0) {
            ox = fmaxf(ox, 0.0f);
            oy = fmaxf(oy, 0.0f);
            *(float2*)&g_act[(size_t)dst * HID + lane * 2] = make_float2(ox, oy);
        } else {
            *(float2*)&outp[(size_t)dst * HID + lane * 2] = make_float2(ox, oy);
        }
    }
}

extern "C" void kernel_launch(void* const* d_in, const int* in_sizes, int n_in,
                              void* d_out, int out_size)
{
    const float* x  = (const float*)d_in[0];
    const void*  ei = d_in[1];               // int32 or int64, device-detected
    const float* ew = (const float*)d_in[2];
    const float* W1 = (const float*)d_in[3];
    const float* b1 = (const float*)d_in[4];
    const float* W2 = (const float*)d_in[5];
    const float* b2 = (const float*)d_in[6];
    float* out = (float*)d_out;

    int n = in_sizes[0] / HID;
    int E = in_sizes[2];

    const int T = 256;
    int gN   = (n + T - 1) / T;              // 391
    int gE   = (E + T - 1) / T;              // 4688
    const int AGG_BLOCKS = 148 * 8;          // one full resident wave
    const int AGG_WARPS  = AGG_BLOCKS * (T / 32);

    init_kernel      <<<gN, T>>>(ei, n);                         // 0
    hist_gemm1_kernel<<<gE + gN, T>>>(ei, ew, x, W1, n, E, gE);  // 1
    scanbin_kernel   <<<gE, T>>>(ei, ew, n, E, gN);              // 2

    agg_kernel<0><<<AGG_BLOCKS, T>>>(b1, nullptr, n, AGG_WARPS); // 3 (profiled)
    gemm2_kernel <<<gN, T>>>(W2, n);                             // 4
    agg_kernel<1><<<AGG_BLOCKS, T>>>(b2, out, n, AGG_WARPS);     // 5
}